// round 8
// baseline (speedup 1.0000x reference)
#include <cuda_runtime.h>
#include <cstdint>

// Problem constants (fixed by the dataset)
#define KMAX      24     // max n-grams per word
#define ROW_BYTES 512    // E=128 fp32
#define VMAX      32768  // >= vocab size (32000)

// Zero row: padded slot ids are 0 and must contribute zero (reference zeroes
// table row 0; raw input row 0 is NOT zero). Static .bss device global.
__device__ __align__(256) float g_zero_row[128];

// Dedup scratch: per-vocab-word mean embedding + "appears in batch" flags.
// Static device globals = allowed scratch.
__device__ unsigned int g_flags[VMAX / 4];          // byte flags, uint-backed
__device__ __align__(256) float4 g_scratch[VMAX * 32];  // [V,128] f32 = 16.8MB

// 256-bit table gather, L2 evict_last (keep the 102MB table resident in the
// 126MB L2 across graph replays).
__device__ __forceinline__ void ldg256_evl(const void* p, uint64_t d[4]) {
    asm("ld.global.nc.L2::evict_last.v4.b64 {%0,%1,%2,%3}, [%4];"
        : "=l"(d[0]), "=l"(d[1]), "=l"(d[2]), "=l"(d[3])
        : "l"(p));
}

// ---------------------------------------------------------------- kernel 1
__global__ void clear_flags_kernel() {
    const int i = blockIdx.x * blockDim.x + threadIdx.x;
    if (i < VMAX / 4) g_flags[i] = 0u;
}

// ---------------------------------------------------------------- kernel 2
__global__ void mark_kernel(const int* __restrict__ word_idx, int n_words) {
    const int i = blockIdx.x * blockDim.x + threadIdx.x;
    if (i < n_words)
        ((unsigned char*)g_flags)[word_idx[i]] = 1;  // racy idempotent store
}

// ---------------------------------------------------------------- kernel 3
// One warp per vocab word that appears in the batch (~63% of 32000).
// Each LDG.256 fetches TWO ngram rows (lanes 0-15 even slot, 16-31 odd);
// warp-uniform trip count ceil(cnt/2). Result -> g_scratch[v].
__global__ __launch_bounds__(256, 6)
void compute_kernel(const int* __restrict__ ngram_ids,
                    const int* __restrict__ ngram_counts,
                    const char* __restrict__ emb,    // byte view of table
                    int vocab) {
    const int v    = (blockIdx.x * blockDim.x + threadIdx.x) >> 5;
    const int lane = threadIdx.x & 31;
    if (v >= vocab) return;
    if (((const unsigned char*)g_flags)[v] == 0) return;  // warp-uniform

    const int half = lane >> 4;       // 0: even slots, 1: odd slots
    const int sub  = lane & 15;       // 32B chunk within the 512B row

    int id_l = 0;
    if (lane < KMAX) id_l = __ldg(&ngram_ids[v * KMAX + lane]);
    const int cnt = __ldg(&ngram_counts[v]);
    const int pairs = (cnt + 1) >> 1;   // warp-uniform trip count

    const char* zrow = (const char*)g_zero_row + sub * 32;

    float acc[8];
    #pragma unroll
    for (int i = 0; i < 8; ++i) acc[i] = 0.f;

    #pragma unroll
    for (int t = 0; t < KMAX / 2; ++t) {
        if (t >= pairs) break;          // warp-uniform: no divergence
        const int id = __shfl_sync(0xffffffffu, id_l, 2 * t + half);
        const void* p = id ? (const void*)(emb + (size_t)id * ROW_BYTES + sub * 32)
                           : (const void*)zrow;   // padded slot -> zero row
        uint64_t d[4];
        ldg256_evl(p, d);
        #pragma unroll
        for (int i = 0; i < 4; ++i) {
            acc[2 * i + 0] += __uint_as_float((uint32_t)d[i]);
            acc[2 * i + 1] += __uint_as_float((uint32_t)(d[i] >> 32));
        }
    }

    #pragma unroll
    for (int i = 0; i < 8; ++i)
        acc[i] += __shfl_xor_sync(0xffffffffu, acc[i], 16);

    const float inv = 1.0f / (float)cnt;
    if (half == 0) {
        float4 r;
        r.x = acc[0] * inv; r.y = acc[1] * inv;
        r.z = acc[2] * inv; r.w = acc[3] * inv;
        float4 r2;
        r2.x = acc[4] * inv; r2.y = acc[5] * inv;
        r2.z = acc[6] * inv; r2.w = acc[7] * inv;
        g_scratch[(size_t)v * 32 + sub * 2 + 0] = r;
        g_scratch[(size_t)v * 32 + sub * 2 + 1] = r2;
    }
}

// ---------------------------------------------------------------- kernel 4
// out[i] = scratch[word_idx[i]]. Scratch was just written -> L2 resident.
// Output written with __stwt (write-through) so the 16.8MB stream never
// allocates dirty L2 lines that would churn the table.
__global__ __launch_bounds__(256)
void scatter_kernel(const int* __restrict__ word_idx,
                    float4* __restrict__ out,       // [n_words*32] float4
                    int n_words) {
    const int i = blockIdx.x * blockDim.x + threadIdx.x;   // one float4 each
    if (i >= n_words * 32) return;
    const int w = __ldg(&word_idx[i >> 5]);                // warp-uniform
    const float4 v = __ldg(&g_scratch[(size_t)w * 32 + (i & 31)]);
    __stwt(&out[i], v);
}

extern "C" void kernel_launch(void* const* d_in, const int* in_sizes, int n_in,
                              void* d_out, int out_size) {
    const int*   word_idx     = (const int*)d_in[0];   // [B*S]
    const int*   ngram_ids    = (const int*)d_in[1];   // [V*24]
    const int*   ngram_counts = (const int*)d_in[2];   // [V]
    const char*  emb_table    = (const char*)d_in[3];  // [NG*128] f32
    float4*      outp         = (float4*)d_out;

    const int n_words = in_sizes[0];                   // 32768
    const int vocab   = in_sizes[2];                   // 32000

    // 1) clear flags
    clear_flags_kernel<<<(VMAX / 4 + 255) / 256, 256>>>();
    // 2) mark words that appear
    mark_kernel<<<(n_words + 255) / 256, 256>>>(word_idx, n_words);
    // 3) per-unique-word mean embedding (warp per vocab word)
    compute_kernel<<<(vocab * 32 + 255) / 256, 256>>>(ngram_ids, ngram_counts,
                                                      emb_table, vocab);
    // 4) scatter to output positions
    scatter_kernel<<<(n_words * 32 + 255) / 256, 256>>>(word_idx, outp, n_words);
}

// round 10
// speedup vs baseline: 1.0656x; 1.0656x over previous
#include <cuda_runtime.h>
#include <cstdint>

// Problem constants (fixed by the dataset)
#define KMAX      24     // max n-grams per word
#define ROW_BYTES 512    // E=128 fp32
#define VMAX      32768  // >= vocab size (32000)

// Zero row: padded slot ids are 0 and must contribute zero (reference zeroes
// table row 0; raw input row 0 is NOT zero). Static .bss device global.
__device__ __align__(256) float g_zero_row[128];

// Dedup scratch: per-vocab-word mean embedding + "appears in batch" flags.
__device__ unsigned int g_flags[VMAX / 4];              // byte flags
__device__ __align__(256) float4 g_scratch[VMAX * 32];  // [V,128] f32 = 16.8MB

// 256-bit table gather, L2 evict_last (keep the 102MB table L2-resident).
__device__ __forceinline__ void ldg256_evl(const void* p, uint64_t d[4]) {
    asm("ld.global.nc.L2::evict_last.v4.b64 {%0,%1,%2,%3}, [%4];"
        : "=l"(d[0]), "=l"(d[1]), "=l"(d[2]), "=l"(d[3])
        : "l"(p));
}

// Plain 256-bit load (scratch reads; freshly dirty in L2, default policy).
__device__ __forceinline__ void ldg256(const void* p, uint64_t d[4]) {
    asm("ld.global.nc.v4.b64 {%0,%1,%2,%3}, [%4];"
        : "=l"(d[0]), "=l"(d[1]), "=l"(d[2]), "=l"(d[3])
        : "l"(p));
}

// 256-bit output store, L2 evict_first (16.8MB stream, never re-read; do not
// churn table lines, but DO coalesce in L2 — unlike st.wt).
// NOTE: evict qualifiers on st require the .v4.b64 (256-bit) form on this
// toolchain — 128-bit evict_first does not assemble.
__device__ __forceinline__ void stg256_evf(void* p, const uint64_t d[4]) {
    asm volatile("st.global.L2::evict_first.v4.b64 [%0], {%1,%2,%3,%4};"
                 :: "l"(p), "l"(d[0]), "l"(d[1]), "l"(d[2]), "l"(d[3])
                 : "memory");
}

// ---------------------------------------------------------------- kernel 1
__global__ void clear_flags_kernel() {
    const int i = blockIdx.x * blockDim.x + threadIdx.x;
    if (i < VMAX / 4) g_flags[i] = 0u;
}

// ---------------------------------------------------------------- kernel 2
__global__ void mark_kernel(const int* __restrict__ word_idx, int n_words) {
    const int i = blockIdx.x * blockDim.x + threadIdx.x;
    if (i < n_words)
        ((unsigned char*)g_flags)[word_idx[i]] = 1;  // racy idempotent store
}

// ---------------------------------------------------------------- kernel 3
// One warp per vocab word that appears in the batch (~63% of 32000).
// Each LDG.256 fetches TWO ngram rows (lanes 0-15 even slot, 16-31 odd);
// warp-uniform trip count ceil(cnt/2). Result -> g_scratch[v].
__global__ __launch_bounds__(256, 6)
void compute_kernel(const int* __restrict__ ngram_ids,
                    const int* __restrict__ ngram_counts,
                    const char* __restrict__ emb,    // byte view of table
                    int vocab) {
    const int v    = (blockIdx.x * blockDim.x + threadIdx.x) >> 5;
    const int lane = threadIdx.x & 31;
    if (v >= vocab) return;
    if (((const unsigned char*)g_flags)[v] == 0) return;  // warp-uniform

    const int half = lane >> 4;       // 0: even slots, 1: odd slots
    const int sub  = lane & 15;       // 32B chunk within the 512B row

    int id_l = 0;
    if (lane < KMAX) id_l = __ldg(&ngram_ids[v * KMAX + lane]);
    const int cnt = __ldg(&ngram_counts[v]);
    const int pairs = (cnt + 1) >> 1;   // warp-uniform trip count

    const char* zrow = (const char*)g_zero_row + sub * 32;

    float acc[8];
    #pragma unroll
    for (int i = 0; i < 8; ++i) acc[i] = 0.f;

    #pragma unroll
    for (int t = 0; t < KMAX / 2; ++t) {
        if (t >= pairs) break;          // warp-uniform: no divergence
        const int id = __shfl_sync(0xffffffffu, id_l, 2 * t + half);
        const void* p = id ? (const void*)(emb + (size_t)id * ROW_BYTES + sub * 32)
                           : (const void*)zrow;   // padded slot -> zero row
        uint64_t d[4];
        ldg256_evl(p, d);
        #pragma unroll
        for (int i = 0; i < 4; ++i) {
            acc[2 * i + 0] += __uint_as_float((uint32_t)d[i]);
            acc[2 * i + 1] += __uint_as_float((uint32_t)(d[i] >> 32));
        }
    }

    #pragma unroll
    for (int i = 0; i < 8; ++i)
        acc[i] += __shfl_xor_sync(0xffffffffu, acc[i], 16);

    const float inv = 1.0f / (float)cnt;
    if (half == 0) {
        float4 r;
        r.x = acc[0] * inv; r.y = acc[1] * inv;
        r.z = acc[2] * inv; r.w = acc[3] * inv;
        float4 r2;
        r2.x = acc[4] * inv; r2.y = acc[5] * inv;
        r2.z = acc[6] * inv; r2.w = acc[7] * inv;
        g_scratch[(size_t)v * 32 + sub * 2 + 0] = r;
        g_scratch[(size_t)v * 32 + sub * 2 + 1] = r2;
    }
}

// ---------------------------------------------------------------- kernel 4
// out[chunk] = scratch[word_idx[chunk>>4]][chunk&15], 32B chunks.
// Each thread handles 4 widely-strided chunks: 4 word_idx loads, then 4
// independent 256-bit scratch loads (MLP=4), then 4 evict_first stores.
__global__ __launch_bounds__(256)
void scatter_kernel(const int* __restrict__ word_idx,
                    char* __restrict__ out,         // byte view of output
                    int n_chunks) {                 // n_words*16
    const int i = blockIdx.x * blockDim.x + threadIdx.x;
    const int stride = n_chunks >> 2;               // 4 strided groups
    if (i >= stride) return;

    int idx[4], w[4];
    #pragma unroll
    for (int j = 0; j < 4; ++j) {
        idx[j] = i + j * stride;
        w[j] = __ldg(&word_idx[idx[j] >> 4]);       // 16 chunks per word row
    }
    uint64_t d[4][4];
    #pragma unroll
    for (int j = 0; j < 4; ++j)                     // 4 loads in flight
        ldg256((const char*)g_scratch + (size_t)w[j] * ROW_BYTES
                                      + (idx[j] & 15) * 32, d[j]);
    #pragma unroll
    for (int j = 0; j < 4; ++j)
        stg256_evf(out + (size_t)idx[j] * 32, d[j]);
}

extern "C" void kernel_launch(void* const* d_in, const int* in_sizes, int n_in,
                              void* d_out, int out_size) {
    const int*   word_idx     = (const int*)d_in[0];   // [B*S]
    const int*   ngram_ids    = (const int*)d_in[1];   // [V*24]
    const int*   ngram_counts = (const int*)d_in[2];   // [V]
    const char*  emb_table    = (const char*)d_in[3];  // [NG*128] f32
    char*        outp         = (char*)d_out;

    const int n_words  = in_sizes[0];                  // 32768
    const int vocab    = in_sizes[2];                  // 32000
    const int n_chunks = n_words * 16;                 // 32B chunks

    clear_flags_kernel<<<(VMAX / 4 + 255) / 256, 256>>>();
    mark_kernel<<<(n_words + 255) / 256, 256>>>(word_idx, n_words);
    compute_kernel<<<(vocab * 32 + 255) / 256, 256>>>(ngram_ids, ngram_counts,
                                                      emb_table, vocab);
    scatter_kernel<<<(n_chunks / 4 + 255) / 256, 256>>>(word_idx, outp,
                                                        n_chunks);
}

// round 11
// speedup vs baseline: 1.1544x; 1.0833x over previous
#include <cuda_runtime.h>
#include <cstdint>

// Problem constants (fixed by the dataset)
#define KMAX      24     // max n-grams per word
#define ROW_BYTES 512    // E=128 fp32
#define VMAX      32768  // >= vocab size (32000)

// Zero row: padded slot ids are 0 and must contribute zero (reference zeroes
// table row 0; raw input row 0 is NOT zero). Static .bss device global.
__device__ __align__(256) float g_zero_row[128];

// Dedup state: claim flag + representative output position per vocab word.
__device__ int g_claim[VMAX];   // 0/1, cleared each launch
__device__ int g_rep[VMAX];     // position that holds the computed row

// 256-bit table gather, L2 evict_last (keep the 102MB table L2-resident).
__device__ __forceinline__ void ldg256_evl(const void* p, uint64_t d[4]) {
    asm("ld.global.nc.L2::evict_last.v4.b64 {%0,%1,%2,%3}, [%4];"
        : "=l"(d[0]), "=l"(d[1]), "=l"(d[2]), "=l"(d[3])
        : "l"(p));
}

// Plain 256-bit load (copy-pass reads of freshly-written out rows).
__device__ __forceinline__ void ldg256(const void* p, uint64_t d[4]) {
    asm("ld.global.nc.v4.b64 {%0,%1,%2,%3}, [%4];"
        : "=l"(d[0]), "=l"(d[1]), "=l"(d[2]), "=l"(d[3])
        : "l"(p));
}

// Plain 256-bit store (compute's direct result rows: re-read by copy pass,
// so default L2 policy).
__device__ __forceinline__ void stg256(void* p, const uint64_t d[4]) {
    asm volatile("st.global.v4.b64 [%0], {%1,%2,%3,%4};"
                 :: "l"(p), "l"(d[0]), "l"(d[1]), "l"(d[2]), "l"(d[3])
                 : "memory");
}

// 256-bit store, L2 evict_first (duplicate rows: never re-read).
__device__ __forceinline__ void stg256_evf(void* p, const uint64_t d[4]) {
    asm volatile("st.global.L2::evict_first.v4.b64 [%0], {%1,%2,%3,%4};"
                 :: "l"(p), "l"(d[0]), "l"(d[1]), "l"(d[2]), "l"(d[3])
                 : "memory");
}

// ---------------------------------------------------------------- kernel 1
__global__ void clear_kernel() {
    const int i = blockIdx.x * blockDim.x + threadIdx.x;
    if (i < VMAX) g_claim[i] = 0;
}

// ---------------------------------------------------------------- kernel 2
// One warp per batch position. First warp to claim a word gathers its mean
// embedding (two ngram rows per LDG.256; warp-uniform trip ceil(cnt/2)) and
// writes it DIRECTLY to out[pos], recording rep[word]=pos. Duplicate-word
// warps exit immediately (their rows are filled by the copy pass).
__global__ __launch_bounds__(256, 6)
void compute_kernel(const int* __restrict__ word_idx,
                    const int* __restrict__ ngram_ids,
                    const int* __restrict__ ngram_counts,
                    const char* __restrict__ emb,    // byte view of table
                    char* __restrict__ out,          // byte view of output
                    int n_words) {
    const int pos  = (blockIdx.x * blockDim.x + threadIdx.x) >> 5;
    const int lane = threadIdx.x & 31;
    if (pos >= n_words) return;

    const int w = __ldg(&word_idx[pos]);

    int old = 0;
    if (lane == 0) old = atomicExch(&g_claim[w], 1);
    old = __shfl_sync(0xffffffffu, old, 0);
    if (old) return;                       // another warp owns this word
    if (lane == 0) g_rep[w] = pos;

    const int half = lane >> 4;       // 0: even slots, 1: odd slots
    const int sub  = lane & 15;       // 32B chunk within the 512B row

    int id_l = 0;
    if (lane < KMAX) id_l = __ldg(&ngram_ids[w * KMAX + lane]);
    const int cnt = __ldg(&ngram_counts[w]);
    const int pairs = (cnt + 1) >> 1;   // warp-uniform trip count

    const char* zrow = (const char*)g_zero_row + sub * 32;

    float acc[8];
    #pragma unroll
    for (int i = 0; i < 8; ++i) acc[i] = 0.f;

    #pragma unroll
    for (int t = 0; t < KMAX / 2; ++t) {
        if (t >= pairs) break;          // warp-uniform: no divergence
        const int id = __shfl_sync(0xffffffffu, id_l, 2 * t + half);
        const void* p = id ? (const void*)(emb + (size_t)id * ROW_BYTES + sub * 32)
                           : (const void*)zrow;   // padded slot -> zero row
        uint64_t d[4];
        ldg256_evl(p, d);
        #pragma unroll
        for (int i = 0; i < 4; ++i) {
            acc[2 * i + 0] += __uint_as_float((uint32_t)d[i]);
            acc[2 * i + 1] += __uint_as_float((uint32_t)(d[i] >> 32));
        }
    }

    #pragma unroll
    for (int i = 0; i < 8; ++i)
        acc[i] += __shfl_xor_sync(0xffffffffu, acc[i], 16);

    const float inv = 1.0f / (float)cnt;
    if (half == 0) {
        uint64_t q[4];
        #pragma unroll
        for (int i = 0; i < 4; ++i) {
            const uint32_t lo = __float_as_uint(acc[2 * i + 0] * inv);
            const uint32_t hi = __float_as_uint(acc[2 * i + 1] * inv);
            q[i] = (uint64_t)lo | ((uint64_t)hi << 32);
        }
        stg256(out + (size_t)pos * ROW_BYTES + sub * 32, q);
    }
}

// ---------------------------------------------------------------- kernel 3
// Fill duplicate positions: out[pos] = out[rep[word_idx[pos]]].
// One thread per 32B chunk; representative positions exit after two small
// loads. Reads hit fresh dirty L2 lines; writes are evict_first.
__global__ __launch_bounds__(256)
void copy_kernel(const int* __restrict__ word_idx,
                 char* __restrict__ out,            // byte view of output
                 int n_chunks) {                    // n_words*16
    const int t = blockIdx.x * blockDim.x + threadIdx.x;
    if (t >= n_chunks) return;
    const int pos = t >> 4;
    const int w = __ldg(&word_idx[pos]);
    const int r = __ldg(&g_rep[w]);
    if (r == pos) return;                 // representative: already written

    uint64_t d[4];
    ldg256(out + (size_t)r * ROW_BYTES + (t & 15) * 32, d);
    stg256_evf(out + (size_t)t * 32, d);
}

extern "C" void kernel_launch(void* const* d_in, const int* in_sizes, int n_in,
                              void* d_out, int out_size) {
    const int*   word_idx     = (const int*)d_in[0];   // [B*S]
    const int*   ngram_ids    = (const int*)d_in[1];   // [V*24]
    const int*   ngram_counts = (const int*)d_in[2];   // [V]
    const char*  emb_table    = (const char*)d_in[3];  // [NG*128] f32
    char*        outp         = (char*)d_out;

    const int n_words  = in_sizes[0];                  // 32768
    const int n_chunks = n_words * 16;                 // 32B chunks

    clear_kernel<<<(VMAX + 255) / 256, 256>>>();
    compute_kernel<<<(n_words * 32 + 255) / 256, 256>>>(word_idx, ngram_ids,
                                                        ngram_counts,
                                                        emb_table, outp,
                                                        n_words);
    copy_kernel<<<(n_chunks + 255) / 256, 256>>>(word_idx, outp, n_chunks);
}

// round 12
// speedup vs baseline: 1.2252x; 1.0613x over previous
#include <cuda_runtime.h>
#include <cstdint>

// Problem constants (fixed by the dataset)
#define KMAX      24     // max n-grams per word
#define ROW_BYTES 512    // E=128 fp32
#define VMAX      32768  // >= vocab size (32000)

// Zero row: padded slot ids are 0 and must contribute zero (reference zeroes
// table row 0; raw input row 0 is NOT zero). Static .bss device global.
__device__ __align__(256) float g_zero_row[128];

// Dedup state: claim flag + representative output position per vocab word.
// g_claim starts zero (.bss) and is RESET to zero by the tail of copy_kernel
// each launch, so every launch (first correctness call and every graph
// replay) sees identical state -> deterministic.
__device__ int g_claim[VMAX];
__device__ int g_rep[VMAX];

// 256-bit table gather, L2 evict_last (keep the 102MB table L2-resident).
__device__ __forceinline__ void ldg256_evl(const void* p, uint64_t d[4]) {
    asm("ld.global.nc.L2::evict_last.v4.b64 {%0,%1,%2,%3}, [%4];"
        : "=l"(d[0]), "=l"(d[1]), "=l"(d[2]), "=l"(d[3])
        : "l"(p));
}

// Plain 256-bit load (copy-pass reads of freshly-written out rows).
__device__ __forceinline__ void ldg256(const void* p, uint64_t d[4]) {
    asm("ld.global.nc.v4.b64 {%0,%1,%2,%3}, [%4];"
        : "=l"(d[0]), "=l"(d[1]), "=l"(d[2]), "=l"(d[3])
        : "l"(p));
}

// Plain 256-bit store (representative rows: re-read by the copy pass).
__device__ __forceinline__ void stg256(void* p, const uint64_t d[4]) {
    asm volatile("st.global.v4.b64 [%0], {%1,%2,%3,%4};"
                 :: "l"(p), "l"(d[0]), "l"(d[1]), "l"(d[2]), "l"(d[3])
                 : "memory");
}

// 256-bit store, L2 evict_first (duplicate rows: never re-read).
__device__ __forceinline__ void stg256_evf(void* p, const uint64_t d[4]) {
    asm volatile("st.global.L2::evict_first.v4.b64 [%0], {%1,%2,%3,%4};"
                 :: "l"(p), "l"(d[0]), "l"(d[1]), "l"(d[2]), "l"(d[3])
                 : "memory");
}

// ---------------------------------------------------------------- kernel 1
// One warp per batch position. First warp to claim a word gathers its mean
// embedding (two ngram rows per LDG.256; warp-uniform trip ceil(cnt/2)) and
// writes it DIRECTLY to out[pos], recording rep[word]=pos. Duplicate-word
// warps exit. ids/cnt are loaded speculatively BEFORE the claim resolves so
// the ~300cyc atomic latency overlaps the id fetch.
__global__ __launch_bounds__(256, 6)
void compute_kernel(const int* __restrict__ word_idx,
                    const int* __restrict__ ngram_ids,
                    const int* __restrict__ ngram_counts,
                    const char* __restrict__ emb,    // byte view of table
                    char* __restrict__ out,          // byte view of output
                    int n_words) {
    const int pos  = (blockIdx.x * blockDim.x + threadIdx.x) >> 5;
    const int lane = threadIdx.x & 31;
    if (pos >= n_words) return;

    const int w = __ldg(&word_idx[pos]);

    // Claim + speculative prologue loads, all in flight together.
    int old = 0;
    if (lane == 0) old = atomicExch(&g_claim[w], 1);
    int id_l = 0;
    if (lane < KMAX) id_l = __ldg(&ngram_ids[w * KMAX + lane]);
    const int cnt = __ldg(&ngram_counts[w]);

    old = __shfl_sync(0xffffffffu, old, 0);
    if (old) return;                       // another warp owns this word
    if (lane == 0) g_rep[w] = pos;

    const int half = lane >> 4;       // 0: even slots, 1: odd slots
    const int sub  = lane & 15;       // 32B chunk within the 512B row
    const int pairs = (cnt + 1) >> 1; // warp-uniform trip count

    const char* zrow = (const char*)g_zero_row + sub * 32;

    float acc[8];
    #pragma unroll
    for (int i = 0; i < 8; ++i) acc[i] = 0.f;

    #pragma unroll
    for (int t = 0; t < KMAX / 2; ++t) {
        if (t >= pairs) break;          // warp-uniform: no divergence
        const int id = __shfl_sync(0xffffffffu, id_l, 2 * t + half);
        const void* p = id ? (const void*)(emb + (size_t)id * ROW_BYTES + sub * 32)
                           : (const void*)zrow;   // padded slot -> zero row
        uint64_t d[4];
        ldg256_evl(p, d);
        #pragma unroll
        for (int i = 0; i < 4; ++i) {
            acc[2 * i + 0] += __uint_as_float((uint32_t)d[i]);
            acc[2 * i + 1] += __uint_as_float((uint32_t)(d[i] >> 32));
        }
    }

    #pragma unroll
    for (int i = 0; i < 8; ++i)
        acc[i] += __shfl_xor_sync(0xffffffffu, acc[i], 16);

    const float inv = 1.0f / (float)cnt;
    if (half == 0) {
        uint64_t q[4];
        #pragma unroll
        for (int i = 0; i < 4; ++i) {
            const uint32_t lo = __float_as_uint(acc[2 * i + 0] * inv);
            const uint32_t hi = __float_as_uint(acc[2 * i + 1] * inv);
            q[i] = (uint64_t)lo | ((uint64_t)hi << 32);
        }
        stg256(out + (size_t)pos * ROW_BYTES + sub * 32, q);
    }
}

// ---------------------------------------------------------------- kernel 2
// Fill duplicate positions: out[pos] = out[rep[word_idx[pos]]], one thread
// per 32B chunk. ALSO resets g_claim for the next launch (threads < VMAX),
// replacing the separate clear kernel (saved ~4us of launch overhead).
__global__ __launch_bounds__(256)
void copy_kernel(const int* __restrict__ word_idx,
                 char* __restrict__ out,            // byte view of output
                 int n_chunks) {                    // n_words*16
    const int t = blockIdx.x * blockDim.x + threadIdx.x;
    if (t < VMAX) g_claim[t] = 0;          // reset for next replay
    if (t >= n_chunks) return;

    const int pos = t >> 4;
    const int w = __ldg(&word_idx[pos]);
    const int r = __ldg(&g_rep[w]);
    if (r == pos) return;                  // representative: already written

    uint64_t d[4];
    ldg256(out + (size_t)r * ROW_BYTES + (t & 15) * 32, d);
    stg256_evf(out + (size_t)t * 32, d);
}

extern "C" void kernel_launch(void* const* d_in, const int* in_sizes, int n_in,
                              void* d_out, int out_size) {
    const int*   word_idx     = (const int*)d_in[0];   // [B*S]
    const int*   ngram_ids    = (const int*)d_in[1];   // [V*24]
    const int*   ngram_counts = (const int*)d_in[2];   // [V]
    const char*  emb_table    = (const char*)d_in[3];  // [NG*128] f32
    char*        outp         = (char*)d_out;

    const int n_words  = in_sizes[0];                  // 32768
    const int n_chunks = n_words * 16;                 // 32B chunks

    compute_kernel<<<(n_words * 32 + 255) / 256, 256>>>(word_idx, ngram_ids,
                                                        ngram_counts,
                                                        emb_table, outp,
                                                        n_words);
    copy_kernel<<<(n_chunks + 255) / 256, 256>>>(word_idx, outp, n_chunks);
}